// round 13
// baseline (speedup 1.0000x reference)
#include <cuda_runtime.h>
#include <cuda_fp16.h>
#include <math.h>
#include <stdint.h>

// Problem constants
#define Bsz   8
#define Ntok  4096
#define Cch   512
#define NHh   8
#define HDd   64
#define MAXPC 321
#define EPSC  1e-6f
#define NCHK  16

// ---------------------------------------------------------------------------
// Scratch (device globals)
// ---------------------------------------------------------------------------
static __device__ float g_KKc[Bsz*NHh*Ntok*64];   // compact signed |k|^p
static __device__ float g_G [Bsz*Ntok*Cch];
static __device__ float g_V [Bsz*Ntok*Cch];
static __device__ float g_VD[Bsz*Ntok*Cch];
static __device__ float g_PKV[Bsz*NHh*NCHK*128*64];
static __device__ float g_PKS[Bsz*NHh*NCHK*128];
static __device__ float g_KM [Bsz*NHh*2*128];     // km, km_rot (fp32)
static __device__ float2 g_Z [Bsz*NHh*Ntok];
static __device__ float g_scale[Cch];
static __device__ float g_power[Cch];
// fp16 operands
static __device__ __half g_QQx [Bsz*NHh*Ntok*128]; // expanded [q_pos|q_neg]
static __device__ __half g_KVCTh[Bsz*NHh*64*128];  // KVC^T hi  [e][d]
static __device__ __half g_KVCTl[Bsz*NHh*64*128];  // KVC^T lo
static __device__ __half g_Xf [Bsz*Ntok*Cch];
static __device__ __half g_XAf[Bsz*Ntok*Cch];
static __device__ __half g_Wqgf[2*Cch*Cch];
static __device__ __half g_Wkvf[2*Cch*Cch];
static __device__ __half g_Wpf [Cch*Cch];

// ---------------------------------------------------------------------------
// mma.sync / cp.async helpers (sm_80-compatible PTX)
// ---------------------------------------------------------------------------
__device__ __forceinline__ uint32_t smem_u32(const void* p) {
    uint32_t a;
    asm("{ .reg .u64 t; cvta.to.shared.u64 t, %1; cvt.u32.u64 %0, t; }"
        : "=r"(a) : "l"(p));
    return a;
}
__device__ __forceinline__ void ldsm4(uint32_t* r, uint32_t addr) {
    asm volatile("ldmatrix.sync.aligned.m8n8.x4.shared.b16 {%0,%1,%2,%3}, [%4];"
        : "=r"(r[0]), "=r"(r[1]), "=r"(r[2]), "=r"(r[3]) : "r"(addr));
}
__device__ __forceinline__ void mma_f16(float* c, const uint32_t* a,
                                        uint32_t b0, uint32_t b1) {
    asm volatile("mma.sync.aligned.m16n8k16.row.col.f32.f16.f16.f32 "
        "{%0,%1,%2,%3}, {%4,%5,%6,%7}, {%8,%9}, {%0,%1,%2,%3};"
        : "+f"(c[0]), "+f"(c[1]), "+f"(c[2]), "+f"(c[3])
        : "r"(a[0]), "r"(a[1]), "r"(a[2]), "r"(a[3]), "r"(b0), "r"(b1));
}
__device__ __forceinline__ void cp_async16(uint32_t daddr, const void* gptr) {
    asm volatile("cp.async.cg.shared.global [%0], [%1], 16;"
                 :: "r"(daddr), "l"(gptr) : "memory");
}
#define CP_COMMIT() asm volatile("cp.async.commit_group;" ::: "memory")
#define CP_WAIT(N)  asm volatile("cp.async.wait_group %0;" :: "n"(N) : "memory")

// ---------------------------------------------------------------------------
// K0: precompute softplus(scale_p), 1+4*sigmoid(power_p)
// ---------------------------------------------------------------------------
__global__ void prep_kernel(const float* __restrict__ scale_p,
                            const float* __restrict__ power_p) {
    int i = threadIdx.x;
    if (i < Cch) {
        float sp = scale_p[i];
        g_scale[i] = (sp > 20.f) ? sp : log1pf(expf(sp));
        float pp = power_p[i];
        g_power[i] = 1.0f + 4.0f / (1.0f + expf(-pp));
    }
}

// ---------------------------------------------------------------------------
// Convert fp32 -> fp16
// ---------------------------------------------------------------------------
__global__ __launch_bounds__(256) void cvt_kernel(
    const float* __restrict__ src, __half* __restrict__ dst, int n4)
{
    int i = blockIdx.x * 256 + threadIdx.x;
    if (i >= n4) return;
    float4 v = ((const float4*)src)[i];
    __half2 a = __floats2half2_rn(v.x, v.y);
    __half2 b = __floats2half2_rn(v.z, v.w);
    uint2 w;
    w.x = *(uint32_t*)&a;
    w.y = *(uint32_t*)&b;
    ((uint2*)dst)[i] = w;
}

// ---------------------------------------------------------------------------
// Tensor GEMM via fp16 mma.sync + cp.async double buffering.
// MODE 0: qg -> QQx fp16 expanded + G   MODE 1: kv -> KKc fp32 + V
// MODE 2: proj (+bias)
// ---------------------------------------------------------------------------
#define SPAD 40                     // smem row stride in halves (80B)
#define MATB (128 * SPAD * 2)       // 10240 B per matrix tile
#define STAGEB (2 * MATB)           // 20480 B per stage (A + B)
#define TCSMEM (2 * STAGEB)         // 40960 B total

template<int MODE>
__global__ __launch_bounds__(256) void tc_gemm(
    const __half* __restrict__ A_g, const __half* __restrict__ B_g,
    const float* __restrict__ aux, float* __restrict__ outp)
{
    extern __shared__ __half dsm[];
    const uint32_t sbase = smem_u32(dsm);
    const int tid = threadIdx.x;
    const int wid = tid >> 5;
    const int lane = tid & 31;
    const int wm = wid >> 2;
    const int wn = wid & 3;
    const int bm = blockIdx.y * 128;
    const int bn = blockIdx.x * 128;

    float acc[4][4][4];
    #pragma unroll
    for (int i = 0; i < 4; i++)
        #pragma unroll
        for (int j = 0; j < 4; j++)
            #pragma unroll
            for (int r = 0; r < 4; r++) acc[i][j][r] = 0.f;

    const int lrow0 = tid >> 2, lj0 = tid & 3;
    const int lrow1 = (tid + 256) >> 2, lj1 = tid & 3;
    const uint32_t lrowa = (uint32_t)(lane & 15) * (SPAD * 2);
    const uint32_t lcola = (uint32_t)(lane >> 4) * 16;

    const __half* srcs[2] = {A_g, B_g};

    {
        #pragma unroll
        for (int mat = 0; mat < 2; mat++) {
            const int rbase = (mat == 0) ? bm : bn;
            cp_async16(sbase + mat * MATB + (uint32_t)(lrow0 * 80 + lj0 * 16),
                       srcs[mat] + (size_t)(rbase + lrow0) * 512 + lj0 * 8);
            cp_async16(sbase + mat * MATB + (uint32_t)(lrow1 * 80 + lj1 * 16),
                       srcs[mat] + (size_t)(rbase + lrow1) * 512 + lj1 * 8);
        }
        CP_COMMIT();
    }

    for (int c = 0; c < 16; c++) {
        const int stage = c & 1;
        if (c + 1 < 16) {
            const int k0 = (c + 1) * 32;
            const uint32_t sb2 = sbase + (uint32_t)((c + 1) & 1) * STAGEB;
            #pragma unroll
            for (int mat = 0; mat < 2; mat++) {
                const int rbase = (mat == 0) ? bm : bn;
                cp_async16(sb2 + mat * MATB + (uint32_t)(lrow0 * 80 + lj0 * 16),
                           srcs[mat] + (size_t)(rbase + lrow0) * 512 + k0 + lj0 * 8);
                cp_async16(sb2 + mat * MATB + (uint32_t)(lrow1 * 80 + lj1 * 16),
                           srcs[mat] + (size_t)(rbase + lrow1) * 512 + k0 + lj1 * 8);
            }
            CP_COMMIT();
            CP_WAIT(1);
        } else {
            CP_WAIT(0);
        }
        __syncthreads();

        const uint32_t sA = sbase + (uint32_t)stage * STAGEB;
        const uint32_t sB = sA + MATB;

        #pragma unroll
        for (int k16 = 0; k16 < 2; k16++) {
            uint32_t ah[4][4], bh[2][4];
            #pragma unroll
            for (int i = 0; i < 4; i++) {
                uint32_t off = (uint32_t)(wm * 64 + i * 16) * (SPAD * 2)
                             + lrowa + k16 * 32 + lcola;
                ldsm4(ah[i], sA + off);
            }
            #pragma unroll
            for (int j2 = 0; j2 < 2; j2++) {
                uint32_t off = (uint32_t)(wn * 32 + j2 * 16) * (SPAD * 2)
                             + lrowa + k16 * 32 + lcola;
                ldsm4(bh[j2], sB + off);
            }
            #pragma unroll
            for (int i = 0; i < 4; i++)
                #pragma unroll
                for (int j2 = 0; j2 < 2; j2++)
                    #pragma unroll
                    for (int s = 0; s < 2; s++)
                        mma_f16(acc[i][j2 * 2 + s], ah[i],
                                bh[j2][s], bh[j2][s + 2]);
        }
        __syncthreads();
    }

    // Epilogue
    const int er = lane >> 2;
    const int ec = (lane & 3) * 2;
    #pragma unroll
    for (int i = 0; i < 4; i++) {
        #pragma unroll
        for (int r2 = 0; r2 < 2; r2++) {
            const int m = bm + wm * 64 + i * 16 + er + r2 * 8;
            const int bz = m >> 12, tok = m & 4095;
            const int pemod = tok % MAXPC;
            #pragma unroll
            for (int j = 0; j < 4; j++) {
                #pragma unroll
                for (int r1 = 0; r1 < 2; r1++) {
                    const int col = bn + wn * 32 + j * 8 + ec + r1;
                    const float v0 = acc[i][j][r2 * 2 + r1];
                    if (MODE == 2) {
                        outp[(size_t)m * 512 + col] = v0 + aux[col];
                    } else if (bn < 512) {
                        float v = v0;
                        if (MODE == 1)
                            v += aux[(size_t)pemod * 512 + col];
                        v = v / g_scale[col];
                        const float p = g_power[col];
                        const float aq = fabsf(v);
                        float rr = (aq > 0.f) ? __powf(aq, p) : 0.f;
                        if (v < 0.f) rr = -rr;
                        if (v == 0.f) rr = 0.f;
                        const int h = col >> 6, d = col & 63;
                        const size_t rowi = (size_t)((bz * NHh + h) * Ntok + tok);
                        if (MODE == 0) {
                            __half* dst = g_QQx + rowi * 128 + d;
                            dst[0]  = __float2half(fmaxf(rr, 0.f));
                            dst[64] = __float2half(fmaxf(-rr, 0.f));
                        } else {
                            g_KKc[rowi * 64 + d] = rr;
                        }
                    } else {
                        float* dst = (MODE == 0 ? g_G : g_V);
                        dst[(size_t)m * 512 + (col - 512)] = v0;
                    }
                }
            }
        }
    }
}

// ---------------------------------------------------------------------------
// K3a: per (chunk, b*h) partial KV = KK^T @ Vhead + colsums  (FFMA)
// ---------------------------------------------------------------------------
__global__ __launch_bounds__(256) void kv_partial() {
    const int chunk = blockIdx.x;
    const int bh    = blockIdx.y;
    const int b = bh >> 3, h = bh & 7;
    __shared__ float KKs[32][128];
    __shared__ float Vs[32][64];
    const int tid = threadIdx.x;
    const int d0 = (tid & 31) << 2;
    const int e0 = (tid >> 5) << 3;

    float acc[4][8];
    #pragma unroll
    for (int i = 0; i < 4; i++)
        #pragma unroll
        for (int j = 0; j < 8; j++) acc[i][j] = 0.f;
    float ks = 0.f;

    const int TPC = Ntok / NCHK;
    const float* KKb = g_KKc + ((size_t)bh * Ntok + (size_t)chunk * TPC) * 64;
    const float* Vb  = g_V + ((size_t)(b * Ntok + chunk * TPC)) * Cch + h * 64;

    for (int t = 0; t < TPC / 32; t++) {
        #pragma unroll
        for (int l = 0; l < 2; l++) {
            int fidx = tid + l * 256;
            int r = fidx >> 4, d4 = (fidx & 15) << 2;
            float4 rv = *(const float4*)(KKb + (size_t)(t * 32 + r) * 64 + d4);
            KKs[r][d4+0] = fmaxf(rv.x, 0.f); KKs[r][64+d4+0] = fmaxf(-rv.x, 0.f);
            KKs[r][d4+1] = fmaxf(rv.y, 0.f); KKs[r][64+d4+1] = fmaxf(-rv.y, 0.f);
            KKs[r][d4+2] = fmaxf(rv.z, 0.f); KKs[r][64+d4+2] = fmaxf(-rv.z, 0.f);
            KKs[r][d4+3] = fmaxf(rv.w, 0.f); KKs[r][64+d4+3] = fmaxf(-rv.w, 0.f);
        }
        #pragma unroll
        for (int l = 0; l < 2; l++) {
            int fidx = tid + l * 256;
            int r = fidx >> 4, e4 = (fidx & 15) << 2;
            *(float4*)&Vs[r][e4] =
                *(const float4*)(Vb + (size_t)(t * 32 + r) * Cch + e4);
        }
        __syncthreads();
        #pragma unroll
        for (int r = 0; r < 32; r++) {
            float4 a = *(float4*)&KKs[r][d0];
            float4 b0 = *(float4*)&Vs[r][e0];
            float4 b1 = *(float4*)&Vs[r][e0 + 4];
            float av[4] = {a.x, a.y, a.z, a.w};
            float bv[8] = {b0.x, b0.y, b0.z, b0.w, b1.x, b1.y, b1.z, b1.w};
            #pragma unroll
            for (int i = 0; i < 4; i++)
                #pragma unroll
                for (int j = 0; j < 8; j++)
                    acc[i][j] = fmaf(av[i], bv[j], acc[i][j]);
        }
        if (tid < 128) {
            float s = 0.f;
            #pragma unroll
            for (int r = 0; r < 32; r++) s += KKs[r][tid];
            ks += s;
        }
        __syncthreads();
    }

    float* P = g_PKV + ((size_t)(bh * NCHK + chunk) * 128) * 64;
    #pragma unroll
    for (int i = 0; i < 4; i++)
        #pragma unroll
        for (int j = 0; j < 8; j++)
            P[(size_t)(d0 + i) * 64 + e0 + j] = acc[i][j];
    if (tid < 128)
        g_PKS[(size_t)(bh * NCHK + chunk) * 128 + tid] = ks;
}

// ---------------------------------------------------------------------------
// K3b: reduce chunks -> KVC^T hi/lo fp16 (rotation folded), km/km_rot fp32
// ---------------------------------------------------------------------------
__global__ __launch_bounds__(256) void kv_reduce() {
    const int bh = blockIdx.x;
    const int tid = threadIdx.x;
    const float inv_n = 1.0f / (float)Ntok;
    for (int p = tid; p < 128 * 64; p += 256) {
        int d = p >> 6, e = p & 63;
        int dsrc = (e < 32) ? d : ((d + 64) & 127);
        float s = 0.f;
        #pragma unroll
        for (int c2 = 0; c2 < NCHK; c2++)
            s += g_PKV[((size_t)(bh * NCHK + c2) * 128 + dsrc) * 64 + e];
        s *= inv_n;
        __half hv = __float2half(s);
        __half lv = __float2half(s - __half2float(hv));
        g_KVCTh[((size_t)bh * 64 + e) * 128 + d] = hv;
        g_KVCTl[((size_t)bh * 64 + e) * 128 + d] = lv;
    }
    if (tid < 128) {
        int d = tid, dr = (d + 64) & 127;
        float s1 = 0.f, s2 = 0.f;
        #pragma unroll
        for (int c2 = 0; c2 < NCHK; c2++) {
            s1 += g_PKS[(size_t)(bh * NCHK + c2) * 128 + d];
            s2 += g_PKS[(size_t)(bh * NCHK + c2) * 128 + dr];
        }
        g_KM[(size_t)bh * 256 + d]       = s1 * inv_n;
        g_KM[(size_t)bh * 256 + 128 + d] = s2 * inv_n;
    }
}

// ---------------------------------------------------------------------------
// K4a: per-token z dots (expanded fp16 QQx, 128-wide)
// ---------------------------------------------------------------------------
__global__ __launch_bounds__(256) void z_kernel() {
    const int bh = blockIdx.y;
    const int tile = blockIdx.x;
    __shared__ float km[128], km2[128];
    const int tid = threadIdx.x;
    if (tid < 128) {
        km [tid] = g_KM[(size_t)bh * 256 + tid];
        km2[tid] = g_KM[(size_t)bh * 256 + 128 + tid];
    }
    __syncthreads();
    const int warp = tid >> 5, lane = tid & 31;
    const int d0 = lane * 4;
    for (int it = 0; it < 32; it++) {
        int tok = tile * 256 + warp * 32 + it;
        uint2 qw = *(const uint2*)(g_QQx + ((size_t)bh * Ntok + tok) * 128 + d0);
        __half2 q01 = *(__half2*)&qw.x;
        __half2 q23 = *(__half2*)&qw.y;
        float q0 = __low2float(q01), q1 = __high2float(q01);
        float q2 = __low2float(q23), q3 = __high2float(q23);
        float p1 = q0*km [d0] + q1*km [d0+1] + q2*km [d0+2] + q3*km [d0+3];
        float p2 = q0*km2[d0] + q1*km2[d0+1] + q2*km2[d0+2] + q3*km2[d0+3];
        #pragma unroll
        for (int o = 16; o > 0; o >>= 1) {
            p1 += __shfl_down_sync(0xffffffffu, p1, o);
            p2 += __shfl_down_sync(0xffffffffu, p2, o);
        }
        if (lane == 0)
            g_Z[(size_t)bh * Ntok + tok] = make_float2(p1, p2);
    }
}

// ---------------------------------------------------------------------------
// K4: attention apply via fp16 HMMA.
// A = QQx [tok][128] K-major, B = KVCT hi/lo [e][128] K-major.
// M=128/block, N=64, K=128 in 2 slabs of 64. Warps 2m x 4n (64x16 tiles).
// Epilogue: /(z+eps), +VD, *G -> fp16 XAf.
// ---------------------------------------------------------------------------
__global__ __launch_bounds__(256) void attn_mma() {
    const int bh = blockIdx.y;
    const int m0 = blockIdx.x * 128;
    const int b = bh >> 3, h = bh & 7;
    __shared__ __half sA[128 * 72];
    __shared__ __half sBh[64 * 72];
    __shared__ __half sBl[64 * 72];
    const int tid = threadIdx.x;
    const int wid = tid >> 5;
    const int lane = tid & 31;
    const int wm = wid >> 2;   // 0..1
    const int wn = wid & 3;    // 0..3
    const uint32_t aA = smem_u32(sA);
    const uint32_t aBh = smem_u32(sBh);
    const uint32_t aBl = smem_u32(sBl);

    float acc[4][2][4];
    #pragma unroll
    for (int i = 0; i < 4; i++)
        #pragma unroll
        for (int s = 0; s < 2; s++)
            #pragma unroll
            for (int r = 0; r < 4; r++) acc[i][s][r] = 0.f;

    const __half* Ab  = g_QQx + ((size_t)bh * Ntok + m0) * 128;
    const __half* Bhb = g_KVCTh + (size_t)bh * 64 * 128;
    const __half* Blb = g_KVCTl + (size_t)bh * 64 * 128;

    const uint32_t lr = (uint32_t)(lane & 15) * 144;
    const uint32_t lc = (uint32_t)(lane >> 4) * 16;

    for (int k0 = 0; k0 < 128; k0 += 64) {
        #pragma unroll
        for (int l = 0; l < 4; l++) {
            int idx = tid + l * 256;       // 1024 chunks for A
            int row = idx >> 3, cc = idx & 7;
            cp_async16(aA + (uint32_t)(row * 144 + cc * 16),
                       Ab + (size_t)row * 128 + k0 + cc * 8);
        }
        #pragma unroll
        for (int l = 0; l < 2; l++) {
            int idx = tid + l * 256;       // 512 chunks each for Bh/Bl
            int row = idx >> 3, cc = idx & 7;
            cp_async16(aBh + (uint32_t)(row * 144 + cc * 16),
                       Bhb + (size_t)row * 128 + k0 + cc * 8);
            cp_async16(aBl + (uint32_t)(row * 144 + cc * 16),
                       Blb + (size_t)row * 128 + k0 + cc * 8);
        }
        CP_COMMIT();
        CP_WAIT(0);
        __syncthreads();

        #pragma unroll
        for (int k16 = 0; k16 < 4; k16++) {
            uint32_t a[4][4], bhf[4], blf[4];
            #pragma unroll
            for (int i = 0; i < 4; i++)
                ldsm4(a[i], aA + (uint32_t)((wm * 64 + i * 16) * 144)
                             + lr + k16 * 32 + lc);
            ldsm4(bhf, aBh + (uint32_t)((wn * 16) * 144) + lr + k16 * 32 + lc);
            ldsm4(blf, aBl + (uint32_t)((wn * 16) * 144) + lr + k16 * 32 + lc);
            #pragma unroll
            for (int i = 0; i < 4; i++)
                #pragma unroll
                for (int s = 0; s < 2; s++) {
                    mma_f16(acc[i][s], a[i], bhf[s], bhf[s + 2]);
                    mma_f16(acc[i][s], a[i], blf[s], blf[s + 2]);
                }
        }
        __syncthreads();
    }

    // Epilogue
    const int er = lane >> 2;
    const int ec = (lane & 3) * 2;
    #pragma unroll
    for (int i = 0; i < 4; i++) {
        #pragma unroll
        for (int r2 = 0; r2 < 2; r2++) {
            const int m = m0 + wm * 64 + i * 16 + er + r2 * 8;
            float2 z = g_Z[(size_t)bh * Ntok + m];
            #pragma unroll
            for (int s = 0; s < 2; s++) {
                const int col = wn * 16 + s * 8 + ec;
                const float zv = (col < 32) ? z.x : z.y;
                const float inv = 1.0f / (zv + EPSC);
                const size_t off = ((size_t)(b * Ntok + m)) * Cch + h * 64 + col;
                float2 vd = *(const float2*)(g_VD + off);
                float2 gg = *(const float2*)(g_G + off);
                float r0 = (acc[i][s][r2 * 2 + 0] * inv + vd.x) * gg.x;
                float r1 = (acc[i][s][r2 * 2 + 1] * inv + vd.y) * gg.y;
                __half2 pp = __floats2half2_rn(r0, r1);
                *(uint32_t*)(g_XAf + off) = *(uint32_t*)&pp;
            }
        }
    }
}

// ---------------------------------------------------------------------------
// K5: depthwise 5x5 conv on the (c2, y, x2) view of v
// ---------------------------------------------------------------------------
__global__ __launch_bounds__(256) void dwconv(const float* __restrict__ Wc,
                                              const float* __restrict__ Bc) {
    const int ytile = blockIdx.x;
    const int c2 = blockIdx.y;
    const int b  = blockIdx.z;
    __shared__ float sIn[132][12];
    __shared__ float sW[25];
    __shared__ float sB;
    const int tid = threadIdx.x;
    if (tid < 25) sW[tid] = Wc[c2 * 25 + tid];
    if (tid == 25) sB = Bc[c2];
    const int y0 = ytile * 128;
    const int h = c2 >> 3;
    const int nhi = (c2 & 7) * 512;

    for (int idx = tid; idx < 132 * 12; idx += 256) {
        int sy = idx / 12, sx = idx % 12;
        int yy = y0 - 2 + sy;
        int xx = sx - 2;
        float v = 0.f;
        if (xx >= 0 && xx < 8 && yy >= 0 && yy < 4096) {
            int n = nhi + (yy >> 3);
            int d = ((yy & 7) << 3) + xx;
            v = g_V[((size_t)(b * Ntok + n)) * Cch + h * 64 + d];
        }
        sIn[sy][sx] = v;
    }
    __syncthreads();

    const int x2 = tid & 7;
    const int yl0 = tid >> 3;
    #pragma unroll
    for (int j = 0; j < 4; j++) {
        int yl = yl0 + j * 32;
        float a = sB;
        #pragma unroll
        for (int dy = 0; dy < 5; dy++)
            #pragma unroll
            for (int dx = 0; dx < 5; dx++)
                a = fmaf(sW[dy * 5 + dx], sIn[yl + dy][x2 + dx], a);
        int y = y0 + yl;
        int cc = c2 * 8 + (y >> 9);
        int nn = ((y & 511) << 3) + x2;
        g_VD[((size_t)(b * Ntok + nn)) * Cch + cc] = a;
    }
}

// ---------------------------------------------------------------------------
extern "C" void kernel_launch(void* const* d_in, const int* in_sizes, int n_in,
                              void* d_out, int out_size) {
    const float* x       = (const float*)d_in[0];
    const float* qg_w    = (const float*)d_in[1];
    const float* kv_w    = (const float*)d_in[2];
    const float* proj_w  = (const float*)d_in[3];
    const float* proj_b  = (const float*)d_in[4];
    const float* power_p = (const float*)d_in[5];
    const float* scale_p = (const float*)d_in[6];
    const float* pos_emb = (const float*)d_in[7];
    const float* dwc_w   = (const float*)d_in[8];
    const float* dwc_b   = (const float*)d_in[9];
    float* out = (float*)d_out;

    __half *p_Xf, *p_XAf, *p_Wqgf, *p_Wkvf, *p_Wpf;
    cudaGetSymbolAddress((void**)&p_Xf,   g_Xf);
    cudaGetSymbolAddress((void**)&p_XAf,  g_XAf);
    cudaGetSymbolAddress((void**)&p_Wqgf, g_Wqgf);
    cudaGetSymbolAddress((void**)&p_Wkvf, g_Wkvf);
    cudaGetSymbolAddress((void**)&p_Wpf,  g_Wpf);

    cudaFuncSetAttribute(tc_gemm<0>, cudaFuncAttributeMaxDynamicSharedMemorySize, TCSMEM);
    cudaFuncSetAttribute(tc_gemm<1>, cudaFuncAttributeMaxDynamicSharedMemorySize, TCSMEM);
    cudaFuncSetAttribute(tc_gemm<2>, cudaFuncAttributeMaxDynamicSharedMemorySize, TCSMEM);

    prep_kernel<<<1, 512>>>(scale_p, power_p);
    cvt_kernel<<<16384, 256>>>(x, p_Xf, Bsz * Ntok * Cch / 4);
    cvt_kernel<<<512, 256>>>(qg_w, p_Wqgf, 2 * Cch * Cch / 4);
    cvt_kernel<<<512, 256>>>(kv_w, p_Wkvf, 2 * Cch * Cch / 4);
    cvt_kernel<<<256, 256>>>(proj_w, p_Wpf, Cch * Cch / 4);

    tc_gemm<0><<<dim3(8, 256), 256, TCSMEM>>>(p_Xf, p_Wqgf, nullptr, nullptr);
    tc_gemm<1><<<dim3(8, 256), 256, TCSMEM>>>(p_Xf, p_Wkvf, pos_emb, nullptr);

    kv_partial<<<dim3(NCHK, 64), 256>>>();
    kv_reduce<<<64, 256>>>();
    z_kernel<<<dim3(16, 64), 256>>>();
    dwconv<<<dim3(32, 64, 8), 256>>>(dwc_w, dwc_b);
    attn_mma<<<dim3(32, 64), 256>>>();

    tc_gemm<2><<<dim3(4, 256), 256, TCSMEM>>>(p_XAf, p_Wpf, proj_b, out);
}

// round 15
// speedup vs baseline: 1.0324x; 1.0324x over previous
#include <cuda_runtime.h>
#include <cuda_fp16.h>
#include <math.h>
#include <stdint.h>

// Problem constants
#define Bsz   8
#define Ntok  4096
#define Cch   512
#define NHh   8
#define HDd   64
#define MAXPC 321
#define EPSC  1e-6f
#define NCHK  16

// ---------------------------------------------------------------------------
// Scratch (device globals)
// ---------------------------------------------------------------------------
static __device__ float g_QQc[Bsz*NHh*Ntok*64];   // compact signed |q|^p
static __device__ float g_KKc[Bsz*NHh*Ntok*64];   // compact signed |k|^p
static __device__ float g_G [Bsz*Ntok*Cch];
static __device__ float g_V [Bsz*Ntok*Cch];
static __device__ float g_VD[Bsz*Ntok*Cch];
static __device__ float g_PKV[Bsz*NHh*NCHK*128*64];
static __device__ float g_PKS[Bsz*NHh*NCHK*128];
static __device__ float g_KVC[Bsz*NHh*128*66];
static __device__ float2 g_Z [Bsz*NHh*Ntok];
static __device__ float g_scale[Cch];
static __device__ float g_power[Cch];
// fp16 operands
static __device__ __half g_Xf [Bsz*Ntok*Cch];
static __device__ __half g_XAf[Bsz*Ntok*Cch];
static __device__ __half g_Wqgf[2*Cch*Cch];
static __device__ __half g_Wkvf[2*Cch*Cch];
static __device__ __half g_Wpf [Cch*Cch];

// ---------------------------------------------------------------------------
// mma.sync / cp.async helpers (sm_80-compatible PTX)
// ---------------------------------------------------------------------------
__device__ __forceinline__ uint32_t smem_u32(const void* p) {
    uint32_t a;
    asm("{ .reg .u64 t; cvta.to.shared.u64 t, %1; cvt.u32.u64 %0, t; }"
        : "=r"(a) : "l"(p));
    return a;
}
__device__ __forceinline__ void ldsm4(uint32_t* r, uint32_t addr) {
    asm volatile("ldmatrix.sync.aligned.m8n8.x4.shared.b16 {%0,%1,%2,%3}, [%4];"
        : "=r"(r[0]), "=r"(r[1]), "=r"(r[2]), "=r"(r[3]) : "r"(addr));
}
__device__ __forceinline__ void mma_f16(float* c, const uint32_t* a,
                                        uint32_t b0, uint32_t b1) {
    asm volatile("mma.sync.aligned.m16n8k16.row.col.f32.f16.f16.f32 "
        "{%0,%1,%2,%3}, {%4,%5,%6,%7}, {%8,%9}, {%0,%1,%2,%3};"
        : "+f"(c[0]), "+f"(c[1]), "+f"(c[2]), "+f"(c[3])
        : "r"(a[0]), "r"(a[1]), "r"(a[2]), "r"(a[3]), "r"(b0), "r"(b1));
}
__device__ __forceinline__ void cp_async16(uint32_t daddr, const void* gptr) {
    asm volatile("cp.async.cg.shared.global [%0], [%1], 16;"
                 :: "r"(daddr), "l"(gptr) : "memory");
}
#define CP_COMMIT() asm volatile("cp.async.commit_group;" ::: "memory")
#define CP_WAIT(N)  asm volatile("cp.async.wait_group %0;" :: "n"(N) : "memory")

// ---------------------------------------------------------------------------
// K0: precompute softplus(scale_p), 1+4*sigmoid(power_p)
// ---------------------------------------------------------------------------
__global__ void prep_kernel(const float* __restrict__ scale_p,
                            const float* __restrict__ power_p) {
    int i = threadIdx.x;
    if (i < Cch) {
        float sp = scale_p[i];
        g_scale[i] = (sp > 20.f) ? sp : log1pf(expf(sp));
        float pp = power_p[i];
        g_power[i] = 1.0f + 4.0f / (1.0f + expf(-pp));
    }
}

// ---------------------------------------------------------------------------
// Convert fp32 -> fp16
// ---------------------------------------------------------------------------
__global__ __launch_bounds__(256) void cvt_kernel(
    const float* __restrict__ src, __half* __restrict__ dst, int n4)
{
    int i = blockIdx.x * 256 + threadIdx.x;
    if (i >= n4) return;
    float4 v = ((const float4*)src)[i];
    __half2 a = __floats2half2_rn(v.x, v.y);
    __half2 b = __floats2half2_rn(v.z, v.w);
    uint2 w;
    w.x = *(uint32_t*)&a;
    w.y = *(uint32_t*)&b;
    ((uint2*)dst)[i] = w;
}

// ---------------------------------------------------------------------------
// Fused qg+kv GEMM via fp16 mma.sync + cp.async double buffering.
// grid (16, 256): blockIdx.x < 8 -> qg tile, else kv tile (+pos_emb).
// C[m][c] = sum_k A[m][k]*B[c][k], K=512. Block 128x128, 8 warps (2x4),
// warp tile 64x32, K-chunk 32, 2 stages.
// ---------------------------------------------------------------------------
#define SPAD 40                     // smem row stride in halves (80B)
#define MATB (128 * SPAD * 2)       // 10240 B per matrix tile
#define STAGEB (2 * MATB)           // 20480 B per stage (A + B)
#define TCSMEM (2 * STAGEB)         // 40960 B total

__global__ __launch_bounds__(256) void tc_gemm_qgkv(
    const __half* __restrict__ A_g, const __half* __restrict__ Bqg_g,
    const __half* __restrict__ Bkv_g, const float* __restrict__ pos_emb)
{
    extern __shared__ __half dsm[];
    const uint32_t sbase = smem_u32(dsm);
    const int tid = threadIdx.x;
    const int wid = tid >> 5;
    const int lane = tid & 31;
    const int wm = wid >> 2;
    const int wn = wid & 3;
    const int bm = blockIdx.y * 128;
    const bool is_qg = blockIdx.x < 8;
    const int bn = (is_qg ? blockIdx.x : blockIdx.x - 8) * 128;
    const __half* B_g = is_qg ? Bqg_g : Bkv_g;

    float acc[4][4][4];
    #pragma unroll
    for (int i = 0; i < 4; i++)
        #pragma unroll
        for (int j = 0; j < 4; j++)
            #pragma unroll
            for (int r = 0; r < 4; r++) acc[i][j][r] = 0.f;

    const int lrow0 = tid >> 2, lj0 = tid & 3;
    const int lrow1 = (tid + 256) >> 2, lj1 = tid & 3;
    const uint32_t lrowa = (uint32_t)(lane & 15) * (SPAD * 2);
    const uint32_t lcola = (uint32_t)(lane >> 4) * 16;

    const __half* srcs[2] = {A_g, B_g};

    {
        #pragma unroll
        for (int mat = 0; mat < 2; mat++) {
            const int rbase = (mat == 0) ? bm : bn;
            cp_async16(sbase + mat * MATB + (uint32_t)(lrow0 * 80 + lj0 * 16),
                       srcs[mat] + (size_t)(rbase + lrow0) * 512 + lj0 * 8);
            cp_async16(sbase + mat * MATB + (uint32_t)(lrow1 * 80 + lj1 * 16),
                       srcs[mat] + (size_t)(rbase + lrow1) * 512 + lj1 * 8);
        }
        CP_COMMIT();
    }

    for (int c = 0; c < 16; c++) {
        const int stage = c & 1;
        if (c + 1 < 16) {
            const int k0 = (c + 1) * 32;
            const uint32_t sb2 = sbase + (uint32_t)((c + 1) & 1) * STAGEB;
            #pragma unroll
            for (int mat = 0; mat < 2; mat++) {
                const int rbase = (mat == 0) ? bm : bn;
                cp_async16(sb2 + mat * MATB + (uint32_t)(lrow0 * 80 + lj0 * 16),
                           srcs[mat] + (size_t)(rbase + lrow0) * 512 + k0 + lj0 * 8);
                cp_async16(sb2 + mat * MATB + (uint32_t)(lrow1 * 80 + lj1 * 16),
                           srcs[mat] + (size_t)(rbase + lrow1) * 512 + k0 + lj1 * 8);
            }
            CP_COMMIT();
            CP_WAIT(1);
        } else {
            CP_WAIT(0);
        }
        __syncthreads();

        const uint32_t sA = sbase + (uint32_t)stage * STAGEB;
        const uint32_t sB = sA + MATB;

        #pragma unroll
        for (int k16 = 0; k16 < 2; k16++) {
            uint32_t ah[4][4], bh[2][4];
            #pragma unroll
            for (int i = 0; i < 4; i++) {
                uint32_t off = (uint32_t)(wm * 64 + i * 16) * (SPAD * 2)
                             + lrowa + k16 * 32 + lcola;
                ldsm4(ah[i], sA + off);
            }
            #pragma unroll
            for (int j2 = 0; j2 < 2; j2++) {
                uint32_t off = (uint32_t)(wn * 32 + j2 * 16) * (SPAD * 2)
                             + lrowa + k16 * 32 + lcola;
                ldsm4(bh[j2], sB + off);
            }
            #pragma unroll
            for (int i = 0; i < 4; i++)
                #pragma unroll
                for (int j2 = 0; j2 < 2; j2++)
                    #pragma unroll
                    for (int s = 0; s < 2; s++)
                        mma_f16(acc[i][j2 * 2 + s], ah[i],
                                bh[j2][s], bh[j2][s + 2]);
        }
        __syncthreads();
    }

    // Epilogue
    const int er = lane >> 2;
    const int ec = (lane & 3) * 2;
    #pragma unroll
    for (int i = 0; i < 4; i++) {
        #pragma unroll
        for (int r2 = 0; r2 < 2; r2++) {
            const int m = bm + wm * 64 + i * 16 + er + r2 * 8;
            const int bz = m >> 12, tok = m & 4095;
            const int pemod = tok % MAXPC;
            #pragma unroll
            for (int j = 0; j < 4; j++) {
                #pragma unroll
                for (int r1 = 0; r1 < 2; r1++) {
                    const int col = bn + wn * 32 + j * 8 + ec + r1;
                    const float v0 = acc[i][j][r2 * 2 + r1];
                    if (col < 512) {
                        float v = v0;
                        if (!is_qg)
                            v += pos_emb[(size_t)pemod * 512 + col];
                        v = v / g_scale[col];
                        const float p = g_power[col];
                        const float aq = fabsf(v);
                        float rr = (aq > 0.f) ? __powf(aq, p) : 0.f;
                        if (v < 0.f) rr = -rr;
                        if (v == 0.f) rr = 0.f;
                        const int h = col >> 6, d = col & 63;
                        float* dst = (is_qg ? g_QQc : g_KKc);
                        dst[((size_t)((bz * NHh + h) * Ntok + tok)) * 64 + d] = rr;
                    } else {
                        float* dst = (is_qg ? g_G : g_V);
                        dst[(size_t)m * 512 + (col - 512)] = v0;
                    }
                }
            }
        }
    }
}

// ---------------------------------------------------------------------------
// Proj GEMM (fp16 HMMA, +bias) — identical structure
// ---------------------------------------------------------------------------
__global__ __launch_bounds__(256) void tc_gemm_proj(
    const __half* __restrict__ A_g, const __half* __restrict__ B_g,
    const float* __restrict__ bias, float* __restrict__ outp)
{
    extern __shared__ __half dsm[];
    const uint32_t sbase = smem_u32(dsm);
    const int tid = threadIdx.x;
    const int wid = tid >> 5;
    const int lane = tid & 31;
    const int wm = wid >> 2;
    const int wn = wid & 3;
    const int bm = blockIdx.y * 128;
    const int bn = blockIdx.x * 128;

    float acc[4][4][4];
    #pragma unroll
    for (int i = 0; i < 4; i++)
        #pragma unroll
        for (int j = 0; j < 4; j++)
            #pragma unroll
            for (int r = 0; r < 4; r++) acc[i][j][r] = 0.f;

    const int lrow0 = tid >> 2, lj0 = tid & 3;
    const int lrow1 = (tid + 256) >> 2, lj1 = tid & 3;
    const uint32_t lrowa = (uint32_t)(lane & 15) * (SPAD * 2);
    const uint32_t lcola = (uint32_t)(lane >> 4) * 16;

    const __half* srcs[2] = {A_g, B_g};

    {
        #pragma unroll
        for (int mat = 0; mat < 2; mat++) {
            const int rbase = (mat == 0) ? bm : bn;
            cp_async16(sbase + mat * MATB + (uint32_t)(lrow0 * 80 + lj0 * 16),
                       srcs[mat] + (size_t)(rbase + lrow0) * 512 + lj0 * 8);
            cp_async16(sbase + mat * MATB + (uint32_t)(lrow1 * 80 + lj1 * 16),
                       srcs[mat] + (size_t)(rbase + lrow1) * 512 + lj1 * 8);
        }
        CP_COMMIT();
    }

    for (int c = 0; c < 16; c++) {
        const int stage = c & 1;
        if (c + 1 < 16) {
            const int k0 = (c + 1) * 32;
            const uint32_t sb2 = sbase + (uint32_t)((c + 1) & 1) * STAGEB;
            #pragma unroll
            for (int mat = 0; mat < 2; mat++) {
                const int rbase = (mat == 0) ? bm : bn;
                cp_async16(sb2 + mat * MATB + (uint32_t)(lrow0 * 80 + lj0 * 16),
                           srcs[mat] + (size_t)(rbase + lrow0) * 512 + k0 + lj0 * 8);
                cp_async16(sb2 + mat * MATB + (uint32_t)(lrow1 * 80 + lj1 * 16),
                           srcs[mat] + (size_t)(rbase + lrow1) * 512 + k0 + lj1 * 8);
            }
            CP_COMMIT();
            CP_WAIT(1);
        } else {
            CP_WAIT(0);
        }
        __syncthreads();

        const uint32_t sA = sbase + (uint32_t)stage * STAGEB;
        const uint32_t sB = sA + MATB;

        #pragma unroll
        for (int k16 = 0; k16 < 2; k16++) {
            uint32_t ah[4][4], bh[2][4];
            #pragma unroll
            for (int i = 0; i < 4; i++) {
                uint32_t off = (uint32_t)(wm * 64 + i * 16) * (SPAD * 2)
                             + lrowa + k16 * 32 + lcola;
                ldsm4(ah[i], sA + off);
            }
            #pragma unroll
            for (int j2 = 0; j2 < 2; j2++) {
                uint32_t off = (uint32_t)(wn * 32 + j2 * 16) * (SPAD * 2)
                             + lrowa + k16 * 32 + lcola;
                ldsm4(bh[j2], sB + off);
            }
            #pragma unroll
            for (int i = 0; i < 4; i++)
                #pragma unroll
                for (int j2 = 0; j2 < 2; j2++)
                    #pragma unroll
                    for (int s = 0; s < 2; s++)
                        mma_f16(acc[i][j2 * 2 + s], ah[i],
                                bh[j2][s], bh[j2][s + 2]);
        }
        __syncthreads();
    }

    const int er = lane >> 2;
    const int ec = (lane & 3) * 2;
    #pragma unroll
    for (int i = 0; i < 4; i++) {
        #pragma unroll
        for (int r2 = 0; r2 < 2; r2++) {
            const int m = bm + wm * 64 + i * 16 + er + r2 * 8;
            #pragma unroll
            for (int j = 0; j < 4; j++) {
                #pragma unroll
                for (int r1 = 0; r1 < 2; r1++) {
                    const int col = bn + wn * 32 + j * 8 + ec + r1;
                    outp[(size_t)m * 512 + col] = acc[i][j][r2 * 2 + r1] + bias[col];
                }
            }
        }
    }
}

// ---------------------------------------------------------------------------
// K3a: per (chunk, b*h) partial KV = KK^T @ Vhead + colsums
// ---------------------------------------------------------------------------
__global__ __launch_bounds__(256) void kv_partial() {
    const int chunk = blockIdx.x;
    const int bh    = blockIdx.y;
    const int b = bh >> 3, h = bh & 7;
    __shared__ float KKs[32][128];
    __shared__ float Vs[32][64];
    const int tid = threadIdx.x;
    const int d0 = (tid & 31) << 2;
    const int e0 = (tid >> 5) << 3;

    float acc[4][8];
    #pragma unroll
    for (int i = 0; i < 4; i++)
        #pragma unroll
        for (int j = 0; j < 8; j++) acc[i][j] = 0.f;
    float ks = 0.f;

    const int TPC = Ntok / NCHK;
    const float* KKb = g_KKc + ((size_t)bh * Ntok + (size_t)chunk * TPC) * 64;
    const float* Vb  = g_V + ((size_t)(b * Ntok + chunk * TPC)) * Cch + h * 64;

    for (int t = 0; t < TPC / 32; t++) {
        #pragma unroll
        for (int l = 0; l < 2; l++) {
            int fidx = tid + l * 256;
            int r = fidx >> 4, d4 = (fidx & 15) << 2;
            float4 rv = *(const float4*)(KKb + (size_t)(t * 32 + r) * 64 + d4);
            KKs[r][d4+0] = fmaxf(rv.x, 0.f); KKs[r][64+d4+0] = fmaxf(-rv.x, 0.f);
            KKs[r][d4+1] = fmaxf(rv.y, 0.f); KKs[r][64+d4+1] = fmaxf(-rv.y, 0.f);
            KKs[r][d4+2] = fmaxf(rv.z, 0.f); KKs[r][64+d4+2] = fmaxf(-rv.z, 0.f);
            KKs[r][d4+3] = fmaxf(rv.w, 0.f); KKs[r][64+d4+3] = fmaxf(-rv.w, 0.f);
        }
        #pragma unroll
        for (int l = 0; l < 2; l++) {
            int fidx = tid + l * 256;
            int r = fidx >> 4, e4 = (fidx & 15) << 2;
            *(float4*)&Vs[r][e4] =
                *(const float4*)(Vb + (size_t)(t * 32 + r) * Cch + e4);
        }
        __syncthreads();
        #pragma unroll
        for (int r = 0; r < 32; r++) {
            float4 a = *(float4*)&KKs[r][d0];
            float4 b0 = *(float4*)&Vs[r][e0];
            float4 b1 = *(float4*)&Vs[r][e0 + 4];
            float av[4] = {a.x, a.y, a.z, a.w};
            float bv[8] = {b0.x, b0.y, b0.z, b0.w, b1.x, b1.y, b1.z, b1.w};
            #pragma unroll
            for (int i = 0; i < 4; i++)
                #pragma unroll
                for (int j = 0; j < 8; j++)
                    acc[i][j] = fmaf(av[i], bv[j], acc[i][j]);
        }
        if (tid < 128) {
            float s = 0.f;
            #pragma unroll
            for (int r = 0; r < 32; r++) s += KKs[r][tid];
            ks += s;
        }
        __syncthreads();
    }

    float* P = g_PKV + ((size_t)(bh * NCHK + chunk) * 128) * 64;
    #pragma unroll
    for (int i = 0; i < 4; i++)
        #pragma unroll
        for (int j = 0; j < 8; j++)
            P[(size_t)(d0 + i) * 64 + e0 + j] = acc[i][j];
    if (tid < 128)
        g_PKS[(size_t)(bh * NCHK + chunk) * 128 + tid] = ks;
}

// ---------------------------------------------------------------------------
// K3b: reduce chunks, build KVC with opp-rotation folded in
// ---------------------------------------------------------------------------
__global__ __launch_bounds__(256) void kv_reduce() {
    const int bh = blockIdx.x;
    const int tid = threadIdx.x;
    const float inv_n = 1.0f / (float)Ntok;
    for (int p = tid; p < 128 * 64; p += 256) {
        int d = p >> 6, e = p & 63;
        int dsrc = (e < 32) ? d : ((d + 64) & 127);
        float s = 0.f;
        #pragma unroll
        for (int c2 = 0; c2 < NCHK; c2++)
            s += g_PKV[((size_t)(bh * NCHK + c2) * 128 + dsrc) * 64 + e];
        g_KVC[(size_t)bh * (128 * 66) + d * 66 + e] = s * inv_n;
    }
    if (tid < 128) {
        int d = tid, dr = (d + 64) & 127;
        float s1 = 0.f, s2 = 0.f;
        #pragma unroll
        for (int c2 = 0; c2 < NCHK; c2++) {
            s1 += g_PKS[(size_t)(bh * NCHK + c2) * 128 + d];
            s2 += g_PKS[(size_t)(bh * NCHK + c2) * 128 + dr];
        }
        g_KVC[(size_t)bh * (128 * 66) + d * 66 + 64] = s1 * inv_n;
        g_KVC[(size_t)bh * (128 * 66) + d * 66 + 65] = s2 * inv_n;
    }
}

// ---------------------------------------------------------------------------
// K4a: per-token z dots (compact QQ)
// ---------------------------------------------------------------------------
__global__ __launch_bounds__(256) void z_kernel() {
    const int bh = blockIdx.y;
    const int tile = blockIdx.x;
    __shared__ float km[128], km2[128];
    const int tid = threadIdx.x;
    const float* __restrict__ KVCb = g_KVC + (size_t)bh * (128 * 66);
    if (tid < 128) {
        km [tid] = KVCb[tid * 66 + 64];
        km2[tid] = KVCb[tid * 66 + 65];
    }
    __syncthreads();
    const int warp = tid >> 5, lane = tid & 31;
    const int d0 = lane * 2;
    for (int it = 0; it < 32; it++) {
        int tok = tile * 256 + warp * 32 + it;
        float2 qv = *(const float2*)(g_QQc + ((size_t)bh * Ntok + tok) * 64 + d0);
        float px = fmaxf(qv.x, 0.f), nx = fmaxf(-qv.x, 0.f);
        float py = fmaxf(qv.y, 0.f), ny = fmaxf(-qv.y, 0.f);
        float p1 = px*km [d0] + nx*km [64+d0] + py*km [d0+1] + ny*km [65+d0];
        float p2 = px*km2[d0] + nx*km2[64+d0] + py*km2[d0+1] + ny*km2[65+d0];
        #pragma unroll
        for (int o = 16; o > 0; o >>= 1) {
            p1 += __shfl_down_sync(0xffffffffu, p1, o);
            p2 += __shfl_down_sync(0xffffffffu, p2, o);
        }
        if (lane == 0)
            g_Z[(size_t)bh * Ntok + tok] = make_float2(p1, p2);
    }
}

// ---------------------------------------------------------------------------
// K4: X = QQ @ KVC (compact A, paired B), fused (x+vd)*g -> fp16 XA
// ---------------------------------------------------------------------------
__global__ __launch_bounds__(256) void attn_apply() {
    const int bh = blockIdx.y;
    const int m0 = blockIdx.x * 128;
    const int b = bh >> 3, h = bh & 7;
    __shared__ float As[128][36];
    __shared__ float Bs1[32][64];
    __shared__ float Bs2[32][64];
    const int tid = threadIdx.x;
    const int tm = (tid >> 4) << 3;
    const int tn = (tid & 15) << 2;

    float acc[8][4];
    #pragma unroll
    for (int i = 0; i < 8; i++)
        #pragma unroll
        for (int j = 0; j < 4; j++) acc[i][j] = 0.f;

    const float* Qb = g_QQc + ((size_t)bh * Ntok + m0) * 64;
    const float* KVCb = g_KVC + (size_t)bh * (128 * 66);

    for (int k0 = 0; k0 < 64; k0 += 32) {
        #pragma unroll
        for (int l = 0; l < 4; l++) {
            int fidx = tid + l * 256;
            int row = fidx >> 3, kc = (fidx & 7) << 2;
            *(float4*)&As[row][kc] =
                *(const float4*)(Qb + (size_t)row * 64 + k0 + kc);
        }
        #pragma unroll
        for (int l = 0; l < 8; l++) {
            int idx = tid + l * 256;
            int kk = idx >> 6, n = idx & 63;
            Bs1[kk][n] = KVCb[(k0 + kk) * 66 + n];
            Bs2[kk][n] = KVCb[(k0 + kk + 64) * 66 + n];
        }
        __syncthreads();
        #pragma unroll
        for (int kk = 0; kk < 32; kk++) {
            float4 b1 = *(float4*)&Bs1[kk][tn];
            float4 b2 = *(float4*)&Bs2[kk][tn];
            #pragma unroll
            for (int i = 0; i < 8; i++) {
                float a = As[tm + i][kk];
                float ap = fmaxf(a, 0.f);
                float an = fmaxf(-a, 0.f);
                acc[i][0] = fmaf(ap, b1.x, fmaf(an, b2.x, acc[i][0]));
                acc[i][1] = fmaf(ap, b1.y, fmaf(an, b2.y, acc[i][1]));
                acc[i][2] = fmaf(ap, b1.z, fmaf(an, b2.z, acc[i][2]));
                acc[i][3] = fmaf(ap, b1.w, fmaf(an, b2.w, acc[i][3]));
            }
        }
        __syncthreads();
    }

    #pragma unroll
    for (int i = 0; i < 8; i++) {
        int m = m0 + tm + i;
        float2 z = g_Z[(size_t)bh * Ntok + m];
        float zv = (tn < 32) ? z.x : z.y;
        float inv = 1.0f / (zv + EPSC);
        const size_t off = ((size_t)(b * Ntok + m)) * Cch + h * 64 + tn;
        float4 vd = *(const float4*)(g_VD + off);
        float4 gg = *(const float4*)(g_G + off);
        float r0 = (acc[i][0] * inv + vd.x) * gg.x;
        float r1 = (acc[i][1] * inv + vd.y) * gg.y;
        float r2 = (acc[i][2] * inv + vd.z) * gg.z;
        float r3 = (acc[i][3] * inv + vd.w) * gg.w;
        __half2 pa = __floats2half2_rn(r0, r1);
        __half2 pb = __floats2half2_rn(r2, r3);
        uint2 w;
        w.x = *(uint32_t*)&pa;
        w.y = *(uint32_t*)&pb;
        *(uint2*)(g_XAf + off) = w;
    }
}

// ---------------------------------------------------------------------------
// K5: depthwise 5x5 conv on the (c2, y, x2) view of v
// ---------------------------------------------------------------------------
__global__ __launch_bounds__(256) void dwconv(const float* __restrict__ Wc,
                                              const float* __restrict__ Bc) {
    const int ytile = blockIdx.x;
    const int c2 = blockIdx.y;
    const int b  = blockIdx.z;
    __shared__ float sIn[132][12];
    __shared__ float sW[25];
    __shared__ float sB;
    const int tid = threadIdx.x;
    if (tid < 25) sW[tid] = Wc[c2 * 25 + tid];
    if (tid == 25) sB = Bc[c2];
    const int y0 = ytile * 128;
    const int h = c2 >> 3;
    const int nhi = (c2 & 7) * 512;

    for (int idx = tid; idx < 132 * 12; idx += 256) {
        int sy = idx / 12, sx = idx % 12;
        int yy = y0 - 2 + sy;
        int xx = sx - 2;
        float v = 0.f;
        if (xx >= 0 && xx < 8 && yy >= 0 && yy < 4096) {
            int n = nhi + (yy >> 3);
            int d = ((yy & 7) << 3) + xx;
            v = g_V[((size_t)(b * Ntok + n)) * Cch + h * 64 + d];
        }
        sIn[sy][sx] = v;
    }
    __syncthreads();

    const int x2 = tid & 7;
    const int yl0 = tid >> 3;
    #pragma unroll
    for (int j = 0; j < 4; j++) {
        int yl = yl0 + j * 32;
        float a = sB;
        #pragma unroll
        for (int dy = 0; dy < 5; dy++)
            #pragma unroll
            for (int dx = 0; dx < 5; dx++)
                a = fmaf(sW[dy * 5 + dx], sIn[yl + dy][x2 + dx], a);
        int y = y0 + yl;
        int cc = c2 * 8 + (y >> 9);
        int nn = ((y & 511) << 3) + x2;
        g_VD[((size_t)(b * Ntok + nn)) * Cch + cc] = a;
    }
}

// ---------------------------------------------------------------------------
extern "C" void kernel_launch(void* const* d_in, const int* in_sizes, int n_in,
                              void* d_out, int out_size) {
    const float* x       = (const float*)d_in[0];
    const float* qg_w    = (const float*)d_in[1];
    const float* kv_w    = (const float*)d_in[2];
    const float* proj_w  = (const float*)d_in[3];
    const float* proj_b  = (const float*)d_in[4];
    const float* power_p = (const float*)d_in[5];
    const float* scale_p = (const float*)d_in[6];
    const float* pos_emb = (const float*)d_in[7];
    const float* dwc_w   = (const float*)d_in[8];
    const float* dwc_b   = (const float*)d_in[9];
    float* out = (float*)d_out;

    __half *p_Xf, *p_XAf, *p_Wqgf, *p_Wkvf, *p_Wpf;
    cudaGetSymbolAddress((void**)&p_Xf,   g_Xf);
    cudaGetSymbolAddress((void**)&p_XAf,  g_XAf);
    cudaGetSymbolAddress((void**)&p_Wqgf, g_Wqgf);
    cudaGetSymbolAddress((void**)&p_Wkvf, g_Wkvf);
    cudaGetSymbolAddress((void**)&p_Wpf,  g_Wpf);

    cudaFuncSetAttribute(tc_gemm_qgkv, cudaFuncAttributeMaxDynamicSharedMemorySize, TCSMEM);
    cudaFuncSetAttribute(tc_gemm_proj, cudaFuncAttributeMaxDynamicSharedMemorySize, TCSMEM);

    prep_kernel<<<1, 512>>>(scale_p, power_p);
    cvt_kernel<<<16384, 256>>>(x, p_Xf, Bsz * Ntok * Cch / 4);
    cvt_kernel<<<512, 256>>>(qg_w, p_Wqgf, 2 * Cch * Cch / 4);
    cvt_kernel<<<512, 256>>>(kv_w, p_Wkvf, 2 * Cch * Cch / 4);
    cvt_kernel<<<256, 256>>>(proj_w, p_Wpf, Cch * Cch / 4);

    tc_gemm_qgkv<<<dim3(16, 256), 256, TCSMEM>>>(p_Xf, p_Wqgf, p_Wkvf, pos_emb);

    kv_partial<<<dim3(NCHK, 64), 256>>>();
    kv_reduce<<<64, 256>>>();
    z_kernel<<<dim3(16, 64), 256>>>();
    dwconv<<<dim3(32, 64, 8), 256>>>(dwc_w, dwc_b);
    attn_apply<<<dim3(32, 64), 256>>>();

    tc_gemm_proj<<<dim3(4, 256), 256, TCSMEM>>>(p_XAf, p_Wpf, proj_b, out);
}